// round 15
// baseline (speedup 1.0000x reference)
#include <cuda_runtime.h>
#include <cuda_fp16.h>
#include <cstdint>

#define BB 4
#define TT 32
#define SS 1024
#define HH 512
#define H2 1024
#define NBLK 128

typedef unsigned long long ull;

// ---------------------------------------------------------------------------
// Scratch (allocation-free: __device__ globals)
// ---------------------------------------------------------------------------
__device__ float g_qf[BB * TT * H2];
__device__ float g_sf[(size_t)BB * SS * H2];
__device__ float g_attn[BB * TT * SS];
__device__ float2 g_pstat[BB][32][TT];
__device__ __align__(16) char gA_hi[8 << 20];  // states fp16 [4096][1024]
__device__ __align__(16) char gB_hi[2 << 20];  // Ws^T fp16 [1024][1024]
__device__ unsigned g_cnt[4];                  // barrier counters (never reset)

__device__ __forceinline__ uint32_t smem_u32(const void* p) {
    uint32_t a;
    asm("{ .reg .u64 t; cvta.to.shared.u64 t, %1; cvt.u32.u64 %0, t; }" : "=r"(a) : "l"(p));
    return a;
}
__device__ __forceinline__ uint32_t pack2h(float a, float b) {
    __half2 h = __floats2half2_rn(a, b);
    return *(uint32_t*)&h;
}
__device__ __forceinline__ uint32_t f16x2_pack(float lo, float hi) {
    uint32_t r;
    asm("cvt.rn.f16x2.f32 %0, %1, %2;" : "=r"(r) : "f"(hi), "f"(lo));
    return r;
}
__device__ __forceinline__ uint32_t tanh_h2(uint32_t x) {
    uint32_t y;
    asm("tanh.approx.f16x2 %0, %1;" : "=r"(y) : "r"(x));
    return y;
}
__device__ __forceinline__ float2 f16x2_unpack(uint32_t p) {
    float lo, hi;
    asm("{ .reg .b16 l, h; mov.b32 {l, h}, %2; cvt.f32.f16 %0, l; cvt.f32.f16 %1, h; }"
        : "=f"(lo), "=f"(hi) : "r"(p));
    return make_float2(lo, hi);
}

#define LDSM_X4(r, a) \
    asm volatile("ldmatrix.sync.aligned.m8n8.x4.shared.b16 {%0,%1,%2,%3}, [%4];" \
                 : "=r"((r)[0]), "=r"((r)[1]), "=r"((r)[2]), "=r"((r)[3]) : "r"(a))

__device__ __forceinline__ void hmma(float* c, const uint32_t* a, uint32_t b0, uint32_t b1) {
    asm volatile(
        "mma.sync.aligned.m16n8k16.row.col.f32.f16.f16.f32 "
        "{%0,%1,%2,%3}, {%4,%5,%6,%7}, {%8,%9}, {%0,%1,%2,%3};"
        : "+f"(c[0]), "+f"(c[1]), "+f"(c[2]), "+f"(c[3])
        : "r"(a[0]), "r"(a[1]), "r"(a[2]), "r"(a[3]), "r"(b0), "r"(b1));
}

#define CP16(s, g) \
    asm volatile("cp.async.cg.shared.global [%0], [%1], 16;" :: "r"(s), "l"(g))
#define CPCOMMIT() asm volatile("cp.async.commit_group;" ::: "memory")
#define CPWAIT1() asm volatile("cp.async.wait_group 1;" ::: "memory")
#define CPWAIT0() asm volatile("cp.async.wait_group 0;" ::: "memory")

// Reset-free global barrier: monotonic counter, ceil-multiple target.
__device__ __forceinline__ void gbar(int i) {
    __syncthreads();
    if (threadIdx.x == 0) {
        __threadfence();
        unsigned arrive = atomicAdd(&g_cnt[i], 1u) + 1u;
        unsigned target = ((arrive - 1u) / NBLK + 1u) * NBLK;
        while (atomicAdd(&g_cnt[i], 0u) < target) __nanosleep(64);
    }
    __syncthreads();
}

// sf tiling: 256(M) x 128(N), K-chunks 64, single fp16 MMA, 144B rows.
#define ROWB 144
#define A_TILE (256 * ROWB)        // 36864
#define B_TILE (128 * ROWB)        // 18432
#define STAGEB (A_TILE + B_TILE)   // 55296
#define DSMEM (TT * H2 * 4)        // 131072 dynamic

__device__ __forceinline__ void load_chunk(uint32_t sst, const char* gAh,
                                           const char* gBh, int c, int tid) {
#pragma unroll
    for (int r = 0; r < 4; r++) {
        int i = r * 512 + tid;
        int row = i >> 3, quad = i & 7;
        CP16(sst + row * ROWB + quad * 16,
             gAh + (size_t)row * 2048 + (size_t)c * 128 + quad * 16);
    }
#pragma unroll
    for (int r = 0; r < 2; r++) {
        int i = r * 512 + tid;
        int row = i >> 3, quad = i & 7;
        CP16(sst + A_TILE + row * ROWB + quad * 16,
             gBh + (size_t)row * 2048 + (size_t)c * 128 + quad * 16);
    }
}

// ---------------------------------------------------------------------------
// THE megakernel: 128 blocks x 512 threads, 5 phases, 4 global barriers.
// ---------------------------------------------------------------------------
__global__ __launch_bounds__(512, 1) void mega(const float* __restrict__ query,
                                               const float* __restrict__ states,
                                               const int* __restrict__ mask,
                                               const float* __restrict__ Wq,
                                               const float* __restrict__ bq,
                                               const float* __restrict__ Ws,
                                               const float* __restrict__ v,
                                               const float* __restrict__ Wc,
                                               const float* __restrict__ bc,
                                               float* __restrict__ out_ctx,
                                               float* __restrict__ out_hid,
                                               float* __restrict__ out_att) {
    extern __shared__ __align__(16) char dynsm[];
    __shared__ float scbuf[TT][32];  // align-phase score staging (4KB static)
    int blk = blockIdx.x, tid = threadIdx.x;
    int lane = tid & 31, warp = tid >> 5;

    // ======================= PHASE 0: fused prelude =========================
    if (blk < 16) {
        // qf = query @ Wq + bq -> g_qf.  block=(tg,b), 2 j-passes of 512.
        int tg = blk & 3, b = blk >> 2, t0 = tg * 8;
        float* q_s = (float*)dynsm;  // [8][512]
        for (int i = tid; i < 8 * HH; i += 512)
            q_s[i] = query[(size_t)(b * TT + t0 + (i >> 9)) * HH + (i & 511)];
        __syncthreads();
#pragma unroll 1
        for (int jj = 0; jj < 2; jj++) {
            int j = jj * 512 + tid;
            float acc[8];
            float bias = bq[j];
#pragma unroll
            for (int i = 0; i < 8; i++) acc[i] = bias;
#pragma unroll 8
            for (int k = 0; k < HH; k++) {
                float w = Wq[(size_t)k * H2 + j];
#pragma unroll
                for (int i = 0; i < 8; i++) acc[i] = fmaf(q_s[i * HH + k], w, acc[i]);
            }
#pragma unroll
            for (int i = 0; i < 8; i++)
                g_qf[(size_t)(b * TT + t0 + i) * H2 + j] = acc[i];
        }
    } else if (blk < 32) {
        // hid_q: out_hid = query @ Wc[1024:] + bc (direct store) + zero out_ctx.
        int local = blk - 16;
        int tg = local & 3, b = local >> 2, t0 = tg * 8;
        float* q_s = (float*)dynsm;  // [8][512]
        for (int i = tid; i < 8 * HH; i += 512)
            q_s[i] = query[(size_t)(b * TT + t0 + (i >> 9)) * HH + (i & 511)];
        // zero slice of out_ctx: 32768 f4 / 16 blocks = 2048; 4 per thread
        float4* zp = (float4*)out_ctx;
#pragma unroll
        for (int r = 0; r < 4; r++)
            zp[local * 2048 + r * 512 + tid] = make_float4(0.f, 0.f, 0.f, 0.f);
        __syncthreads();
        int h = tid;
        float acc[8] = {};
#pragma unroll 8
        for (int k = 0; k < HH; k++) {
            float w = Wc[(size_t)(H2 + k) * HH + h];
#pragma unroll
            for (int i = 0; i < 8; i++) acc[i] = fmaf(q_s[i * HH + k], w, acc[i]);
        }
        float bias = bc[h];
#pragma unroll
        for (int i = 0; i < 8; i++)
            out_hid[(size_t)(b * TT + t0 + i) * HH + h] = bias + acc[i];
    } else if (blk < 64) {
        // prep_B: Ws -> gB_hi transposed fp16. 2 parallel 64x64 tiles x 4 rounds.
        int half = tid >> 8, t2 = tid & 255;
        float* tr = (float*)(dynsm + half * 16640);  // [64][65]
#pragma unroll 1
        for (int rd = 0; rd < 4; rd++) {
            int tile = (blk - 32) * 8 + rd * 2 + half;
            int k0 = (tile & 15) * 64, n0 = (tile >> 4) * 64;
            int ki = t2 >> 2, nq = (t2 & 3) * 16;
#pragma unroll
            for (int j = 0; j < 4; j++) {
                float4 vv = *(const float4*)(Ws + (size_t)(k0 + ki) * H2 + n0 + nq + j * 4);
                tr[(nq + j * 4 + 0) * 65 + ki] = vv.x;
                tr[(nq + j * 4 + 1) * 65 + ki] = vv.y;
                tr[(nq + j * 4 + 2) * 65 + ki] = vv.z;
                tr[(nq + j * 4 + 3) * 65 + ki] = vv.w;
            }
            __syncthreads();
            int nr_l = t2 >> 2, kq = (t2 & 3) * 16;
            int n_g = n0 + nr_l;
#pragma unroll
            for (int j = 0; j < 4; j++) {
                int kr = kq + j * 4;
                ull hi = (ull)pack2h(tr[nr_l * 65 + kr], tr[nr_l * 65 + kr + 1]) |
                         ((ull)pack2h(tr[nr_l * 65 + kr + 2], tr[nr_l * 65 + kr + 3]) << 32);
                *(ull*)(gB_hi + ((size_t)n_g * H2 + k0 + kr) * 2) = hi;
            }
            __syncthreads();
        }
    } else {
        // prep_A: states fp32 -> gA_hi fp16. 64 blocks, 32 float4/thread.
        int base = (blk - 64) * 16384;
#pragma unroll 4
        for (int r = 0; r < 32; r++) {
            int fid = base + r * 512 + tid;
            float4 vvv = *(const float4*)(states + (size_t)fid * 4);
            ull hi = (ull)pack2h(vvv.x, vvv.y) | ((ull)pack2h(vvv.z, vvv.w) << 32);
            *(ull*)(gA_hi + (size_t)fid * 8) = hi;
        }
    }
    gbar(0);

    // ======================= PHASE 1: sf = states @ Ws ======================
    {
        uint32_t sbase = smem_u32(dynsm);
        int nt = blk & 7, mt = blk >> 3;
        int wm = warp >> 2, wn = warp & 3;  // warp tile 64(m) x 32(n)
        const char* gAh = gA_hi + (size_t)(mt * 256) * 2048;
        const char* gBh = gB_hi + (size_t)(nt * 128) * 2048;

        float cacc[4][4][4] = {};
        load_chunk(sbase, gAh, gBh, 0, tid);
        CPCOMMIT();

#pragma unroll 1
        for (int c = 0; c < 16; c++) {
            int cur = c & 1;
            if (c + 1 < 16) {
                load_chunk(sbase + (cur ^ 1) * STAGEB, gAh, gBh, c + 1, tid);
                CPCOMMIT();
                CPWAIT1();
            } else {
                CPWAIT0();
            }
            __syncthreads();
            uint32_t sA = sbase + cur * STAGEB;
            uint32_t sB = sA + A_TILE;
            int r16 = lane & 15, hx = lane >> 4;
#pragma unroll
            for (int k16 = 0; k16 < 4; k16++) {
                int kb = k16 * 32 + hx * 16;
                uint32_t ah[4][4], bh[2][4];
#pragma unroll
                for (int mf = 0; mf < 4; mf++)
                    LDSM_X4(ah[mf], sA + (wm * 64 + mf * 16 + r16) * ROWB + kb);
#pragma unroll
                for (int hh = 0; hh < 2; hh++)
                    LDSM_X4(bh[hh], sB + (wn * 32 + hh * 16 + r16) * ROWB + kb);
#pragma unroll
                for (int mf = 0; mf < 4; mf++)
#pragma unroll
                    for (int nf = 0; nf < 4; nf++)
                        hmma(cacc[mf][nf], ah[mf], bh[nf >> 1][nf & 1],
                             bh[nf >> 1][(nf & 1) + 2]);
            }
            __syncthreads();
        }
        int tg = lane >> 2, tq = lane & 3;
#pragma unroll
        for (int mf = 0; mf < 4; mf++) {
#pragma unroll
            for (int nf = 0; nf < 4; nf++) {
                float* base = g_sf + (size_t)(mt * 256 + wm * 64 + mf * 16 + tg) * H2 +
                              nt * 128 + wn * 32 + nf * 8 + tq * 2;
                float2 v0 = {cacc[mf][nf][0], cacc[mf][nf][1]};
                float2 v1 = {cacc[mf][nf][2], cacc[mf][nf][3]};
                *(float2*)base = v0;
                *(float2*)(base + 8 * H2) = v1;
            }
        }
    }
    gbar(1);

    // ======================= PHASE 2: align + slice stats ===================
    {
        float* qf_s = (float*)dynsm;  // [TT][H2]
        int scb = blk & 31, b = blk >> 5;
        const float4* qsrc = (const float4*)(g_qf + (size_t)b * TT * H2);
        float4* qdst = (float4*)qf_s;
#pragma unroll
        for (int i = 0; i < 16; i++) qdst[tid + i * 512] = qsrc[tid + i * 512];

        int s0 = scb * 32 + warp * 2;
        int msk0 = mask[b * SS + s0];
        int msk1 = mask[b * SS + s0 + 1];
        float4 sv[2][8];
#pragma unroll
        for (int si = 0; si < 2; si++) {
            const float* sfrow = g_sf + ((size_t)(b * SS + s0 + si)) * H2;
#pragma unroll
            for (int u = 0; u < 8; u++)
                sv[si][u] = *(const float4*)(sfrow + u * 128 + lane * 4);
        }
        __syncthreads();

        float* ga = g_attn + (size_t)(b * TT) * SS + s0;
#pragma unroll 1
        for (int t = 0; t < TT; t++) {
            const float* qrow = qf_s + t * H2;
            float a00 = 0.f, a01 = 0.f, a10 = 0.f, a11 = 0.f;
#pragma unroll
            for (int u = 0; u < 8; u++) {
                float4 q = *(const float4*)(qrow + u * 128 + lane * 4);
                float4 vv = __ldg((const float4*)(v + u * 128 + lane * 4));
                uint32_t p0 = tanh_h2(f16x2_pack(q.x + sv[0][u].x, q.y + sv[0][u].y));
                uint32_t p1 = tanh_h2(f16x2_pack(q.z + sv[0][u].z, q.w + sv[0][u].w));
                uint32_t p2 = tanh_h2(f16x2_pack(q.x + sv[1][u].x, q.y + sv[1][u].y));
                uint32_t p3 = tanh_h2(f16x2_pack(q.z + sv[1][u].z, q.w + sv[1][u].w));
                float2 t0 = f16x2_unpack(p0), t1 = f16x2_unpack(p1);
                float2 t2 = f16x2_unpack(p2), t3 = f16x2_unpack(p3);
                a00 = fmaf(t0.x, vv.x, a00);
                a01 = fmaf(t0.y, vv.y, a01);
                a00 = fmaf(t1.x, vv.z, a00);
                a01 = fmaf(t1.y, vv.w, a01);
                a10 = fmaf(t2.x, vv.x, a10);
                a11 = fmaf(t2.y, vv.y, a11);
                a10 = fmaf(t3.x, vv.z, a10);
                a11 = fmaf(t3.y, vv.w, a11);
            }
            float acc0 = a00 + a01;
            float acc1 = a10 + a11;
#pragma unroll
            for (int o = 16; o; o >>= 1) {
                acc0 += __shfl_xor_sync(0xffffffffu, acc0, o);
                acc1 += __shfl_xor_sync(0xffffffffu, acc1, o);
            }
            if (lane == 0) {
                acc0 = msk0 ? acc0 : -1e30f;
                acc1 = msk1 ? acc1 : -1e30f;
                ga[(size_t)t * SS] = acc0;
                ga[(size_t)t * SS + 1] = acc1;
                scbuf[t][warp * 2] = acc0;
                scbuf[t][warp * 2 + 1] = acc1;
            }
        }
        __syncthreads();
        if (tid < TT) {
            int t = tid;
            float m = -1e30f;
#pragma unroll
            for (int s = 0; s < 32; s++) m = fmaxf(m, scbuf[t][s]);
            float l = 0.f;
#pragma unroll
            for (int s = 0; s < 32; s++) l += __expf(scbuf[t][s] - m);
            g_pstat[b][scb][t] = make_float2(m, l);
        }
    }
    gbar(2);

    // ======================= PHASE 3: softmax-normalize + ctx ===============
    {
        int scb = blk & 31, b = blk >> 5;
        int s0 = scb * 32;
        float* aw = (float*)dynsm;             // [TT][32]
        float* stat_m = (float*)(dynsm + 4096);
        float* stat_i = (float*)(dynsm + 4096 + 128);

        if (tid < TT) {
            int t = tid;
            float mx = -1e30f;
#pragma unroll
            for (int i = 0; i < 32; i++) mx = fmaxf(mx, g_pstat[b][i][t].x);
            float tot = 0.f;
#pragma unroll
            for (int i = 0; i < 32; i++) {
                float2 p = g_pstat[b][i][t];
                tot += p.y * __expf(p.x - mx);
            }
            stat_m[t] = mx;
            stat_i[t] = 1.0f / tot;
        }
        __syncthreads();
        for (int i = tid; i < TT * 32; i += 512) {
            int t = i >> 5, sl = i & 31;
            float raw = g_attn[(size_t)(b * TT + t) * SS + s0 + sl];
            aw[t * 32 + sl] = __expf(raw - stat_m[t]) * stat_i[t];
        }
        __syncthreads();

        float* oa = out_att + (size_t)b * SS * TT;
        for (int i = tid; i < 32 * TT; i += 512) {
            int sl = i >> 5, t = i & 31;
            oa[(size_t)(s0 + sl) * TT + t] = aw[t * 32 + sl];
        }

#pragma unroll 1
        for (int p = 0; p < 2; p++) {
            int d = p * 512 + tid;
            float acc[TT] = {};
            const float* sb = states + ((size_t)b * SS + s0) * H2 + d;
#pragma unroll 4
            for (int sl = 0; sl < 32; sl++) {
                float sv = sb[(size_t)sl * H2];
#pragma unroll
                for (int t = 0; t < TT; t++) acc[t] = fmaf(aw[t * 32 + sl], sv, acc[t]);
            }
#pragma unroll
            for (int t = 0; t < TT; t++)
                atomicAdd(&out_ctx[(size_t)(b * TT + t) * H2 + d], acc[t]);
        }
    }
    gbar(3);

    // ======================= PHASE 4: hidden += ctx @ Wc[0:1024] ============
    {
        int tg = blk & 3, b = (blk >> 2) & 3, kc = blk >> 4;  // kc 0..7
        int t0 = tg * 8, k0 = kc * 128;
        int h = tid;
        float* cc = (float*)dynsm;  // [8][128]
        for (int i = tid; i < 8 * 128; i += 512) {
            int r = i >> 7, col = i & 127;
            cc[r * 128 + col] = out_ctx[(size_t)(b * TT + t0 + r) * H2 + k0 + col];
        }
        __syncthreads();
        float acc[8] = {};
#pragma unroll 4
        for (int k = 0; k < 128; k++) {
            float w = Wc[(size_t)(k0 + k) * HH + h];
#pragma unroll
            for (int i = 0; i < 8; i++) acc[i] = fmaf(cc[i * 128 + k], w, acc[i]);
        }
#pragma unroll
        for (int i = 0; i < 8; i++)
            atomicAdd(&out_hid[(size_t)(b * TT + t0 + i) * HH + h], acc[i]);
    }
}

// ---------------------------------------------------------------------------
extern "C" void kernel_launch(void* const* d_in, const int* in_sizes, int n_in,
                              void* d_out, int out_size) {
    const float* query  = (const float*)d_in[0];
    const float* states = (const float*)d_in[1];
    const int*   mask   = (const int*)d_in[2];
    const float* Wq     = (const float*)d_in[3];
    const float* bq     = (const float*)d_in[4];
    const float* Ws     = (const float*)d_in[5];
    const float* v      = (const float*)d_in[6];
    const float* Wc     = (const float*)d_in[7];
    const float* bc     = (const float*)d_in[8];

    float* out_ctx = (float*)d_out;                  // (B,T,2H)
    float* out_hid = out_ctx + BB * TT * H2;         // (B,T,H)
    float* out_att = out_hid + BB * TT * HH;         // (B,S,T)

    static int attr_set = 0;
    if (!attr_set) {
        cudaFuncSetAttribute(mega, cudaFuncAttributeMaxDynamicSharedMemorySize, DSMEM);
        attr_set = 1;
    }

    mega<<<NBLK, 512, DSMEM>>>(query, states, mask, Wq, bq, Ws, v, Wc, bc,
                               out_ctx, out_hid, out_att);
}